// round 1
// baseline (speedup 1.0000x reference)
#include <cuda_runtime.h>
#include <math_constants.h>

#define C1   2048
#define NB   8
#define HH   56
#define WW   56
#define HP   58
#define WP   64

// Scratch (allowed: __device__ globals, no allocation)
__device__ float  g_xpad[NB * 16 * HP * WP];   // 475,136 floats = 1.9 MB, zero-padded halo
__device__ float4 g_rec[C1 * 4 * 3];           // per (oc,j): {w0..w3},{w4..w7},{w8,bias,cin_bits,0}

// ---------------------------------------------------------------------------
// Prep 1: pad + relayout x -> [n][cin][58][64], halo = 0, rows 256B-aligned
// ---------------------------------------------------------------------------
__global__ void pad_x_kernel(const float* __restrict__ x) {
    int i  = blockIdx.x * blockDim.x + threadIdx.x;      // exactly 475,136 threads
    int pw = i & (WP - 1);
    int t  = i >> 6;                                      // WP == 64
    int ph = t % HP;
    int c  = t / HP;                                      // 0..127 (n*16 + cin)
    float v = 0.f;
    int h = ph - 1, w = pw - 1;
    if (h >= 0 && h < HH && w >= 0 && w < WW)
        v = x[(c * HH + h) * WW + w];
    g_xpad[i] = v;
}

// ---------------------------------------------------------------------------
// Prep 2: resolve index (int64 OR int32 at runtime) and gather weight records
// ---------------------------------------------------------------------------
__global__ void wprep_kernel(const float* __restrict__ W1,
                             const float* __restrict__ b1,
                             const unsigned* __restrict__ idxw) {
    int t = blockIdx.x * blockDim.x + threadIdx.x;        // exactly 8192 threads
    // int64 little-endian: odd words are high halves of values < 2^13 -> all 0.
    // int32 permutation of 0..8191: at most one zero among any 4 words.
    unsigned probe = idxw[1] | idxw[3] | idxw[5] | idxw[7];
    unsigned c;
    if (probe == 0u) c = idxw[2 * t];   // int64 payload in low word
    else             c = idxw[t];       // int32
    c &= (C1 - 1);                      // index % 2048

    float wv[9];
#pragma unroll
    for (int k = 0; k < 9; k++) wv[k] = W1[c * 9 + k];
    float b   = b1[c];
    int   cin = (int)(c >> 7);          // 128 conv channels per input channel

    g_rec[t * 3 + 0] = make_float4(wv[0], wv[1], wv[2], wv[3]);
    g_rec[t * 3 + 1] = make_float4(wv[4], wv[5], wv[6], wv[7]);
    g_rec[t * 3 + 2] = make_float4(wv[8], b, __int_as_float(cin), 0.f);
}

// ---------------------------------------------------------------------------
// Packed fp32 FMA (sm_100 FFMA2): d = a*b + d on both lanes
// ---------------------------------------------------------------------------
__device__ __forceinline__ void fma2(float2& d, const float2& a, const float2& b) {
    asm("fma.rn.f32x2 %0, %1, %2, %0;"
        : "+l"(reinterpret_cast<unsigned long long&>(d))
        : "l"(reinterpret_cast<const unsigned long long&>(a)),
          "l"(reinterpret_cast<const unsigned long long&>(b)));
}
__device__ __forceinline__ float2 mk2(float a, float b) { return make_float2(a, b); }

// ---------------------------------------------------------------------------
// Main fused kernel: thread = one 4(h) x 8(w) output patch for one (n, oc).
// conv over 4 gathered channels, running max, bias folded into accumulator.
// ---------------------------------------------------------------------------
__global__ void __launch_bounds__(256, 2) rptn_main_kernel(float* __restrict__ out) {
    int gid  = blockIdx.x * 256 + threadIdx.x;   // exactly 8*2048*98 threads
    int tile = gid % 98;                         // 14 row-groups x 7 col-groups
    int rest = gid / 98;
    int oc   = rest & (C1 - 1);
    int n    = rest >> 11;
    int colg = tile % 7;
    int rowg = tile / 7;
    int h0 = rowg * 4, w0 = colg * 8;

    float2 mx[4][4];
#pragma unroll
    for (int r = 0; r < 4; r++)
#pragma unroll
        for (int p = 0; p < 4; p++)
            mx[r][p] = make_float2(-CUDART_INF_F, -CUDART_INF_F);

    const float4* rec = g_rec + (size_t)oc * 12;         // 4 records of 3 float4
    const float*  xn  = g_xpad + (size_t)n * 16 * HP * WP;

#pragma unroll 1
    for (int j = 0; j < 4; j++) {
        float4 r0 = rec[0], r1 = rec[1], r2 = rec[2];
        rec += 3;
        int cin = __float_as_int(r2.z);

        float wv[9] = {r0.x, r0.y, r0.z, r0.w, r1.x, r1.y, r1.z, r1.w, r2.x};
        float2 wk[9];
#pragma unroll
        for (int k = 0; k < 9; k++) wk[k] = make_float2(wv[k], wv[k]);

        float2 bb = make_float2(r2.y, r2.y);
        float2 acc[4][4];
#pragma unroll
        for (int r = 0; r < 4; r++)
#pragma unroll
            for (int p = 0; p < 4; p++) acc[r][p] = bb;

        const float* bp = xn + ((size_t)cin * HP + h0) * WP + w0;  // padded rows h0..h0+5

#pragma unroll
        for (int pr = 0; pr < 6; pr++) {
            const float* rp = bp + pr * WP;
            float4 A  = *(const float4*)(rp);       // cols w0   .. w0+3  (16B aligned)
            float4 B  = *(const float4*)(rp + 4);   // cols w0+4 .. w0+7
            float2 Cc = *(const float2*)(rp + 8);   // cols w0+8 .. w0+9

            // aligned even pairs: ee[p] = (rv[2p], rv[2p+1]); shift-by-2 is ee[p+1]
            float2 ee[5];
            ee[0] = mk2(A.x, A.y); ee[1] = mk2(A.z, A.w);
            ee[2] = mk2(B.x, B.y); ee[3] = mk2(B.z, B.w);
            ee[4] = Cc;
            // shift-by-1 pairs need packing (only 4 packs per row)
            float2 s1[4];
            s1[0] = mk2(A.y, A.z); s1[1] = mk2(A.w, B.x);
            s1[2] = mk2(B.y, B.z); s1[3] = mk2(B.w, Cc.x);

            int rlo = pr - 2 < 0 ? 0 : pr - 2;
            int rhi = pr < 3 ? pr : 3;
#pragma unroll
            for (int r = 0; r < 4; r++) {
                if (r < rlo || r > rhi) continue;   // folds at compile time
                int dy = pr - r;
#pragma unroll
                for (int p = 0; p < 4; p++) {
                    fma2(acc[r][p], wk[dy * 3 + 0], ee[p]);
                    fma2(acc[r][p], wk[dy * 3 + 1], s1[p]);
                    fma2(acc[r][p], wk[dy * 3 + 2], ee[p + 1]);
                }
            }
        }

#pragma unroll
        for (int r = 0; r < 4; r++)
#pragma unroll
            for (int p = 0; p < 4; p++) {
                mx[r][p].x = fmaxf(mx[r][p].x, acc[r][p].x);
                mx[r][p].y = fmaxf(mx[r][p].y, acc[r][p].y);
            }
    }

    float* ob = out + (((size_t)n * C1 + oc) * HH + h0) * WW + w0;  // offset % 4 == 0
#pragma unroll
    for (int r = 0; r < 4; r++) {
        float4 o0 = make_float4(mx[r][0].x, mx[r][0].y, mx[r][1].x, mx[r][1].y);
        float4 o1 = make_float4(mx[r][2].x, mx[r][2].y, mx[r][3].x, mx[r][3].y);
        *(float4*)(ob + r * WW)     = o0;
        *(float4*)(ob + r * WW + 4) = o1;
    }
}

// ---------------------------------------------------------------------------
extern "C" void kernel_launch(void* const* d_in, const int* in_sizes, int n_in,
                              void* d_out, int out_size) {
    const float*    x   = (const float*)d_in[0];
    const float*    W1  = (const float*)d_in[1];
    const float*    b1  = (const float*)d_in[2];
    const unsigned* idx = (const unsigned*)d_in[3];

    // 8*16*58*64 = 475136 = 1856 * 256
    pad_x_kernel<<<1856, 256>>>(x);
    // 8192 = 32 * 256
    wprep_kernel<<<32, 256>>>(W1, b1, idx);
    // 8*2048*98 = 1,605,632 = 6272 * 256
    rptn_main_kernel<<<6272, 256>>>((float*)d_out);
}